// round 1
// baseline (speedup 1.0000x reference)
#include <cuda_runtime.h>

// Problem constants (fixed by the reference: T=730, B=16384, MLP 8->16->8->1)
#define T_STEPS 730
#define NBASIN  16384
#define NH1     16
#define NH2     8
#define EPSV    1e-5f

// Inputs (metadata order == setup_inputs dict order):
// 0 p_and_e [T,B,2]  1 kc[B]  2 um[B]  3 lm[B]  4 dm[B]  5 b[B]  6 im[B]
// 7 c[B]  8 w0[B]  9 W1[8,16]  10 b1[16]  11 W2[16,8]  12 b2[8]  13 W3[8,1]  14 b3[1]
// Output: [T,B,4] fp32 = (r, rim, e, pe_net)

__global__ __launch_bounds__(128, 1)
void xaj_dpl_kernel(const float2* __restrict__ p_and_e,
                    const float*  __restrict__ kc_,
                    const float*  __restrict__ um_,
                    const float*  __restrict__ lm_,
                    const float*  __restrict__ dm_,
                    const float*  __restrict__ b_,
                    const float*  __restrict__ im_,
                    const float*  __restrict__ c_,
                    const float*  __restrict__ w0_,
                    const float*  __restrict__ W1,
                    const float*  __restrict__ b1,
                    const float*  __restrict__ W2,
                    const float*  __restrict__ b2,
                    const float*  __restrict__ W3,
                    const float*  __restrict__ b3,
                    float4*       __restrict__ out)
{
    // W2 [16,8] broadcast from shared as float4 pairs (conflict-free broadcast LDS.128)
    __shared__ float sW2[NH1 * NH2];
    if (threadIdx.x < NH1 * NH2) sW2[threadIdx.x] = W2[threadIdx.x];
    __syncthreads();

    const int bas = blockIdx.x * blockDim.x + threadIdx.x;

    // Per-basin time-invariant parameters
    const float kc = kc_[bas];
    const float um = um_[bas];
    const float lm = lm_[bas];
    const float dm = dm_[bas];
    const float bb = b_[bas];
    const float im = im_[bas];
    const float cc = c_[bas];
    float w = w0_[bas];

    const float wm      = um + lm + dm;
    const float one_b   = 1.0f + bb;
    const float wmm     = wm * one_b;
    const float inv_b1  = 1.0f / one_b;
    const float inv_wm  = 1.0f / wm;
    const float inv_wmm = 1.0f / wmm;
    const float wm_eps  = wm - EPSV;

    // Fold constant features (kc,um,lm,dm,c) of layer 1 into h1_base once.
    // Keep time-varying weight rows (w0c, prcp, pet) in registers.
    float h1b[NH1], w5[NH1], w6[NH1], w7[NH1];
#pragma unroll
    for (int i = 0; i < NH1; i++) {
        float r0 = W1[0 * NH1 + i];
        float r1 = W1[1 * NH1 + i];
        float r2 = W1[2 * NH1 + i];
        float r3 = W1[3 * NH1 + i];
        float r4 = W1[4 * NH1 + i];
        h1b[i] = b1[i] + kc * r0 + um * r1 + lm * r2 + dm * r3 + cc * r4;
        w5[i] = W1[5 * NH1 + i];
        w6[i] = W1[6 * NH1 + i];
        w7[i] = W1[7 * NH1 + i];
    }
    float rb2[NH2], rw3[NH2];
#pragma unroll
    for (int k = 0; k < NH2; k++) { rb2[k] = b2[k]; rw3[k] = W3[k]; }
    const float rb3 = b3[0];

    // Distance-2 prefetch of forcing data (hides ~577-cyc DRAM latency under the step body)
    const float2* pe_ptr = p_and_e + bas;
    float2 pe_a = pe_ptr[0];
    float2 pe_b = pe_ptr[NBASIN];

    float4* out_ptr = out + bas;

#pragma unroll 1
    for (int t = 0; t < T_STEPS; t++) {
        const float2 pe = pe_a;
        pe_a = pe_b;
        if (t + 2 < T_STEPS) pe_b = pe_ptr[(size_t)(t + 2) * NBASIN];

        const float prcp = fmaxf(pe.x, 0.0f);
        const float pet  = fmaxf(pe.y, 0.0f);
        const float w0c  = fminf(fmaxf(w, 0.0f), wm_eps);

        // ---- evap MLP: layer 1 (folded constants + 3 live features) ----
        float h1[NH1];
#pragma unroll
        for (int i = 0; i < NH1; i++) {
            float h = h1b[i] + w0c * w5[i] + prcp * w6[i] + pet * w7[i];
            h1[i] = fmaxf(h, 0.0f);
        }

        // ---- layer 2: 16x8 matvec, 8 independent accumulators ----
        float acc0 = rb2[0], acc1 = rb2[1], acc2 = rb2[2], acc3 = rb2[3];
        float acc4 = rb2[4], acc5 = rb2[5], acc6 = rb2[6], acc7 = rb2[7];
#pragma unroll
        for (int j = 0; j < NH1; j++) {
            const float4 wA = *reinterpret_cast<const float4*>(&sW2[j * NH2]);
            const float4 wB = *reinterpret_cast<const float4*>(&sW2[j * NH2 + 4]);
            const float hj = h1[j];
            acc0 += hj * wA.x; acc1 += hj * wA.y; acc2 += hj * wA.z; acc3 += hj * wA.w;
            acc4 += hj * wB.x; acc5 += hj * wB.y; acc6 += hj * wB.z; acc7 += hj * wB.w;
        }

        // ---- layer 3 ----
        float y = rb3;
        y += fmaxf(acc0, 0.0f) * rw3[0];
        y += fmaxf(acc1, 0.0f) * rw3[1];
        y += fmaxf(acc2, 0.0f) * rw3[2];
        y += fmaxf(acc3, 0.0f) * rw3[3];
        y += fmaxf(acc4, 0.0f) * rw3[4];
        y += fmaxf(acc5, 0.0f) * rw3[5];
        y += fmaxf(acc6, 0.0f) * rw3[6];
        y += fmaxf(acc7, 0.0f) * rw3[7];

        const float sig = 1.0f / (1.0f + __expf(-y));
        const float e   = sig * kc * pet;

        // ---- XAJ saturation-excess runoff ----
        const float pd     = prcp - e;
        const float pe_net = fmaxf(pd, 0.0f);
        const float frac   = fminf(fmaxf(1.0f - w0c * inv_wm, EPSV), 1.0f);
        const float a      = wmm * (1.0f - __powf(frac, inv_b1));
        const float r_full = pe_net - (wm - w0c);
        const float resid  = fminf(fmaxf(1.0f - (pe_net + a) * inv_wmm, 0.0f), 1.0f);
        // When pe_net + a >= wmm, resid clamps to 0 and __powf(0, 1+b) = 0,
        // so this is branchlessly identical to the reference's where().
        const float r   = fmaxf(r_full + wm * __powf(resid, one_b), 0.0f);
        const float rim = pe_net * im;

        w = fminf(fmaxf(w0c + pd - r, 0.0f), wm_eps);

        out_ptr[(size_t)t * NBASIN] = make_float4(r, rim, e, pe_net);
    }
}

extern "C" void kernel_launch(void* const* d_in, const int* in_sizes, int n_in,
                              void* d_out, int out_size)
{
    (void)in_sizes; (void)n_in; (void)out_size;
    const float2* p_and_e = (const float2*)d_in[0];
    const float*  kc = (const float*)d_in[1];
    const float*  um = (const float*)d_in[2];
    const float*  lm = (const float*)d_in[3];
    const float*  dm = (const float*)d_in[4];
    const float*  b  = (const float*)d_in[5];
    const float*  im = (const float*)d_in[6];
    const float*  c  = (const float*)d_in[7];
    const float*  w0 = (const float*)d_in[8];
    const float*  W1 = (const float*)d_in[9];
    const float*  b1 = (const float*)d_in[10];
    const float*  W2 = (const float*)d_in[11];
    const float*  b2 = (const float*)d_in[12];
    const float*  W3 = (const float*)d_in[13];
    const float*  b3 = (const float*)d_in[14];
    float4* out = (float4*)d_out;

    // 16384 basins: 128 blocks x 128 threads -> 4 warps/block, 1 per SMSP,
    // spread over 128 of 148 SMs (latency-bound regime; max parallelism = B).
    xaj_dpl_kernel<<<128, 128>>>(p_and_e, kc, um, lm, dm, b, im, c, w0,
                                 W1, b1, W2, b2, W3, b3, out);
}